// round 8
// baseline (speedup 1.0000x reference)
#include <cuda_runtime.h>
#include <cuda_bf16.h>
#include <mma.h>
#include <cstdint>
#include <math.h>

#define NN 20000
#define NE 320000
#define NEP 340000
#define NEG_SLOPE 0.2f

using bf16 = __nv_bfloat16;
using namespace nvcuda;

// ---------------- scratch ----------------
__device__ int   g_deg[NN];
__device__ int   g_rowptr[NN + 1];
__device__ int   g_wptr[NN];
__device__ float g_dis[NN];
__device__ int   g_src[NEP];
__device__ int   g_eid[NEP];
__device__ float g_xw[NN * 512];
__device__ bf16  g_xhi[NN * 128];
__device__ bf16  g_xlo[NN * 128];
__device__ bf16  g_hhi[NN * 256];
__device__ bf16  g_hlo[NN * 256];
__device__ bf16  g_wthi[122880];
__device__ bf16  g_wtlo[122880];
__device__ float g_als[NN * 8];
__device__ float g_ald[NN * 8];
__device__ float g_alpha[(long)NEP * 8];

// weight-transpose offsets (elements) in g_wt*  (T[n*K+k] = W[k*N+n])
#define OFF_GCN   0
#define OFF_GAT1  8192
#define OFF_GAT2  24576
#define OFF_MEAN  90112
#define OFF_STD   106496

__device__ __forceinline__ void split_store(bf16* hi, bf16* lo, long idx, float v) {
    bf16 h = __float2bfloat16(v);
    hi[idx] = h;
    lo[idx] = __float2bfloat16(v - __bfloat162float(h));
}

// ---------------- graph build ----------------
__global__ void k_zero_deg() {
    for (int i = blockIdx.x * blockDim.x + threadIdx.x; i < NN; i += gridDim.x * blockDim.x)
        g_deg[i] = 0;
}
__global__ void k_hist(const int* __restrict__ ei) {
    for (int e = blockIdx.x * blockDim.x + threadIdx.x; e < NEP; e += gridDim.x * blockDim.x) {
        int d = (e < NE) ? ei[NE + e] : (e - NE);
        atomicAdd(&g_deg[d], 1);
    }
}
__global__ void k_scan() {
    __shared__ int tmp[1024];
    const int tid = threadIdx.x;
    const int CH = (NN + 1023) / 1024;
    const int base = tid * CH;
    int sum = 0;
    for (int i = 0; i < CH; i++) { int n = base + i; if (n < NN) sum += g_deg[n]; }
    tmp[tid] = sum;
    __syncthreads();
    for (int off = 1; off < 1024; off <<= 1) {
        int v = (tid >= off) ? tmp[tid - off] : 0;
        __syncthreads();
        tmp[tid] += v;
        __syncthreads();
    }
    int run = tmp[tid] - sum;
    for (int i = 0; i < CH; i++) {
        int n = base + i;
        if (n < NN) {
            int c = g_deg[n];
            g_rowptr[n] = run;
            g_wptr[n] = run;
            g_dis[n] = (c > 0) ? rsqrtf((float)c) : 0.0f;
            run += c;
        }
    }
    if (tid == 1023) g_rowptr[NN] = run;
}
__global__ void k_scatter(const int* __restrict__ ei) {
    for (int e = blockIdx.x * blockDim.x + threadIdx.x; e < NEP; e += gridDim.x * blockDim.x) {
        int s, d;
        if (e < NE) { s = ei[e]; d = ei[NE + e]; }
        else        { s = e - NE; d = e - NE; }
        int pos = atomicAdd(&g_wptr[d], 1);
        g_src[pos] = s;
        g_eid[pos] = e;
    }
}

// ---------------- input / weight split kernels ----------------
__global__ void k_xsplit(const float* __restrict__ x) {
    long i = (long)blockIdx.x * blockDim.x + threadIdx.x;
    if (i < (long)NN * 128) split_store(g_xhi, g_xlo, i, x[i]);
}
__global__ void k_wsplit(const float* __restrict__ Wgcn, const float* __restrict__ Wg1,
                         const float* __restrict__ Wg2, const float* __restrict__ Wm,
                         const float* __restrict__ Ws) {
    int i = blockIdx.x * blockDim.x + threadIdx.x;
    if (i >= 122880) return;
    const float* W;
    int K, N, off;
    if      (i < OFF_GAT1) { W = Wgcn; K = 128; N = 64;  off = OFF_GCN;  }
    else if (i < OFF_GAT2) { W = Wg1;  K = 64;  N = 256; off = OFF_GAT1; }
    else if (i < OFF_MEAN) { W = Wg2;  K = 256; N = 256; off = OFF_GAT2; }
    else if (i < OFF_STD)  { W = Wm;   K = 64;  N = 256; off = OFF_MEAN; }
    else                   { W = Ws;   K = 64;  N = 256; off = OFF_STD;  }
    int j = i - off;
    int n = j / K, k = j % K;
    split_store(g_wthi, g_wtlo, i, W[k * N + n]);
}

// ---------------- split-bf16 tensor-core GEMM (wmma; baseline PTX, works on sm_103) ----
// C[M,Ntot] tile [n0, n0+64) = A[M,K] @ T[Ntot,K]^T,  fp32 accum.
// D = Ahi*Bhi + Ahi*Blo + Alo*Bhi.  B (hi+lo) staged in dynamic smem per block.
__global__ __launch_bounds__(256) void k_wmma(
    const bf16* __restrict__ Ahi, const bf16* __restrict__ Alo,
    const bf16* __restrict__ Bhi, const bf16* __restrict__ Blo,
    float* __restrict__ C, int M, int K, int Ntot)
{
    extern __shared__ bf16 sB[];                 // [64*K] hi, then [64*K] lo
    bf16* sBhi = sB;
    bf16* sBlo = sB + 64 * K;
    const int n0 = blockIdx.y * 64;

    // cooperative B tile load (all threads; before any early-exit)
    const int elems = 64 * K;
    for (int u = threadIdx.x * 8; u < elems; u += 256 * 8) {
        *(uint4*)(sBhi + u) = *(const uint4*)(Bhi + (long)n0 * K + u);
        *(uint4*)(sBlo + u) = *(const uint4*)(Blo + (long)n0 * K + u);
    }
    __syncthreads();

    const int warp = threadIdx.x >> 5;
    const int m0 = blockIdx.x * 128 + warp * 16;
    if (m0 >= M) return;

    wmma::fragment<wmma::accumulator, 16, 16, 16, float> acc[4];
    for (int j = 0; j < 4; j++) wmma::fill_fragment(acc[j], 0.0f);

    for (int pass = 0; pass < 3; pass++) {
        const bf16* Ap = (pass == 2) ? Alo : Ahi;
        const bf16* Bp = (pass == 1) ? sBlo : sBhi;
        for (int k = 0; k < K; k += 16) {
            wmma::fragment<wmma::matrix_a, 16, 16, 16, bf16, wmma::row_major> af;
            wmma::load_matrix_sync(af, Ap + (long)m0 * K + k, K);
            for (int j = 0; j < 4; j++) {
                wmma::fragment<wmma::matrix_b, 16, 16, 16, bf16, wmma::col_major> bfr;
                wmma::load_matrix_sync(bfr, Bp + (long)(j * 16) * K + k, K);
                wmma::mma_sync(acc[j], af, bfr, acc[j]);
            }
        }
    }
    for (int j = 0; j < 4; j++)
        wmma::store_matrix_sync(C + (long)m0 * Ntot + n0 + j * 16, acc[j], Ntot,
                                wmma::mem_row_major);
}

// ---------------- GCN aggregate ----------------
__global__ void k_gcn_agg(const float* __restrict__ xw, const float* __restrict__ b) {
    int n = blockIdx.x, t = threadIdx.x;
    int beg = g_rowptr[n], end = g_rowptr[n + 1];
    float dn = g_dis[n];
    float acc = 0.0f;
    for (int j = beg; j < end; j++) {
        int s = g_src[j];
        acc = fmaf(dn * g_dis[s], xw[s * 64 + t], acc);
    }
    float v = fmaxf(acc + b[t], 0.0f);
    split_store(g_hhi, g_hlo, (long)n * 64 + t, v);
}

// ---------------- attention coefficients ----------------
__global__ void k_coef4(const float* __restrict__ xw, const float* __restrict__ asrc,
                        const float* __restrict__ adst) {
    int t = threadIdx.x;
    int n = blockIdx.x * 4 + (t >> 6);
    int u = t & 63;
    int h = u >> 4, q = u & 15;
    const float4 v  = *(const float4*)(xw + (long)n * 256 + h * 64 + q * 4);
    const float4 ws = *(const float4*)(asrc + h * 64 + q * 4);
    const float4 wd = *(const float4*)(adst + h * 64 + q * 4);
    float ps = v.x * ws.x + v.y * ws.y + v.z * ws.z + v.w * ws.w;
    float pd = v.x * wd.x + v.y * wd.y + v.z * wd.z + v.w * wd.w;
    for (int off = 8; off > 0; off >>= 1) {
        ps += __shfl_down_sync(0xffffffffu, ps, off, 16);
        pd += __shfl_down_sync(0xffffffffu, pd, off, 16);
    }
    if (q == 0) {
        g_als[n * 4 + h] = ps;
        g_ald[n * 4 + h] = pd;
    }
}
__global__ void k_coef8(const float* __restrict__ xw,
                        const float* __restrict__ as_m, const float* __restrict__ ad_m,
                        const float* __restrict__ as_s, const float* __restrict__ ad_s) {
    int t = threadIdx.x;
    int n = blockIdx.x * 2 + (t >> 7);
    int u = t & 127;
    int h = u >> 4, q = u & 15;
    const float* aws = (h < 4) ? (as_m + h * 64) : (as_s + (h - 4) * 64);
    const float* awd = (h < 4) ? (ad_m + h * 64) : (ad_s + (h - 4) * 64);
    const float4 v  = *(const float4*)(xw + (long)n * 512 + h * 64 + q * 4);
    const float4 ws = *(const float4*)(aws + q * 4);
    const float4 wd = *(const float4*)(awd + q * 4);
    float ps = v.x * ws.x + v.y * ws.y + v.z * ws.z + v.w * ws.w;
    float pd = v.x * wd.x + v.y * wd.y + v.z * wd.z + v.w * wd.w;
    for (int off = 8; off > 0; off >>= 1) {
        ps += __shfl_down_sync(0xffffffffu, ps, off, 16);
        pd += __shfl_down_sync(0xffffffffu, pd, off, 16);
    }
    if (q == 0) {
        g_als[n * 8 + h] = ps;
        g_ald[n * 8 + h] = pd;
    }
}

__device__ __forceinline__ float leaky(float x) { return x > 0.0f ? x : NEG_SLOPE * x; }

// ---------------- segment softmax ----------------
template <int H>
__global__ void k_softmax(float* __restrict__ out0, float* __restrict__ out1) {
    int warp = threadIdx.x >> 5, lane = threadIdx.x & 31;
    int n = blockIdx.x * 4 + warp;
    if (n >= NN) return;
    int beg = g_rowptr[n], end = g_rowptr[n + 1];
    float ad[H];
    for (int h = 0; h < H; h++) ad[h] = g_ald[n * H + h];
    float m[H];
    for (int h = 0; h < H; h++) m[h] = -1e30f;
    for (int j = beg + lane; j < end; j += 32) {
        int s = g_src[j];
        for (int h = 0; h < H; h++)
            m[h] = fmaxf(m[h], leaky(g_als[s * H + h] + ad[h]));
    }
    for (int h = 0; h < H; h++)
        for (int off = 16; off > 0; off >>= 1)
            m[h] = fmaxf(m[h], __shfl_xor_sync(0xffffffffu, m[h], off));
    float sum[H];
    for (int h = 0; h < H; h++) sum[h] = 0.0f;
    for (int j = beg + lane; j < end; j += 32) {
        int s = g_src[j];
        float ex[H];
        for (int h = 0; h < H; h++) {
            ex[h] = __expf(leaky(g_als[s * H + h] + ad[h]) - m[h]);
            sum[h] += ex[h];
        }
        for (int v = 0; v < H / 4; v++) {
            float4 e4 = make_float4(ex[v * 4], ex[v * 4 + 1], ex[v * 4 + 2], ex[v * 4 + 3]);
            *(float4*)&g_alpha[(long)j * H + v * 4] = e4;
        }
    }
    for (int h = 0; h < H; h++)
        for (int off = 16; off > 0; off >>= 1)
            sum[h] += __shfl_xor_sync(0xffffffffu, sum[h], off);
    float inv[H];
    for (int h = 0; h < H; h++) inv[h] = 1.0f / (sum[h] + 1e-16f);
    for (int j = beg + lane; j < end; j += 32) {
        float ex[H];
        for (int v = 0; v < H / 4; v++) {
            float4 e4 = *(const float4*)&g_alpha[(long)j * H + v * 4];
            ex[v * 4] = e4.x; ex[v * 4 + 1] = e4.y; ex[v * 4 + 2] = e4.z; ex[v * 4 + 3] = e4.w;
        }
        for (int h = 0; h < H; h++) ex[h] *= inv[h];
        for (int v = 0; v < H / 4; v++) {
            float4 e4 = make_float4(ex[v * 4], ex[v * 4 + 1], ex[v * 4 + 2], ex[v * 4 + 3]);
            *(float4*)&g_alpha[(long)j * H + v * 4] = e4;
        }
        int eid = g_eid[j];
        *(float4*)&out0[(long)eid * 4] = make_float4(ex[0], ex[1], ex[2], ex[3]);
        if (H == 8)
            *(float4*)&out1[(long)eid * 4] = make_float4(ex[4], ex[5], ex[6], ex[7]);
    }
}

// ---------------- GAT aggregates ----------------
__global__ void k_agg_concat(const float* __restrict__ xw, const float* __restrict__ b) {
    int n = blockIdx.x, t = threadIdx.x;
    int h = t >> 6;
    int beg = g_rowptr[n], end = g_rowptr[n + 1];
    float acc = 0.0f;
    for (int j = beg; j < end; j++) {
        int s = g_src[j];
        float a = g_alpha[(long)j * 4 + h];
        acc = fmaf(a, xw[(long)s * 256 + t], acc);
    }
    float v = fmaxf(acc + b[t], 0.0f);
    split_store(g_hhi, g_hlo, (long)n * 256 + t, v);
}

__global__ void k_agg_mean(const float* __restrict__ xw, const float* __restrict__ b) {
    __shared__ float sm[256];
    int n = blockIdx.x, t = threadIdx.x;
    int h = t >> 6;
    int beg = g_rowptr[n], end = g_rowptr[n + 1];
    float acc = 0.0f;
    for (int j = beg; j < end; j++) {
        int s = g_src[j];
        float a = g_alpha[(long)j * 4 + h];
        acc = fmaf(a, xw[(long)s * 256 + t], acc);
    }
    sm[t] = acc;
    __syncthreads();
    if (t < 64) {
        float v = (sm[t] + sm[t + 64] + sm[t + 128] + sm[t + 192]) * 0.25f + b[t];
        v = fmaxf(v, 0.0f);
        split_store(g_hhi, g_hlo, (long)n * 64 + t, v);
    }
}

__global__ void k_agg_dual(const float* __restrict__ xw,
                           const float* __restrict__ b_m, const float* __restrict__ b_s,
                           float* __restrict__ out_m, float* __restrict__ out_s) {
    __shared__ float sm[512];
    int n = blockIdx.x, t = threadIdx.x;
    int h = t >> 6;
    int beg = g_rowptr[n], end = g_rowptr[n + 1];
    float acc = 0.0f;
    for (int j = beg; j < end; j++) {
        int s = g_src[j];
        float a = g_alpha[(long)j * 8 + h];
        acc = fmaf(a, xw[(long)s * 512 + t], acc);
    }
    sm[t] = acc;
    __syncthreads();
    if (t < 64) {
        out_m[(long)n * 64 + t] =
            (sm[t] + sm[t + 64] + sm[t + 128] + sm[t + 192]) * 0.25f + b_m[t];
    } else if (t < 128) {
        int u = t - 64;
        out_s[(long)n * 64 + u] =
            (sm[256 + u] + sm[320 + u] + sm[384 + u] + sm[448 + u]) * 0.25f + b_s[u];
    }
}

// ---------------- host driver ----------------
extern "C" void kernel_launch(void* const* d_in, const int* in_sizes, int n_in,
                              void* d_out, int out_size) {
    const float* x        = (const float*)d_in[0];
    const int*   ei       = (const int*)d_in[1];
    const float* gcn_W    = (const float*)d_in[2];
    const float* gcn_b    = (const float*)d_in[3];
    const float* gat1_W   = (const float*)d_in[4];
    const float* gat1_as  = (const float*)d_in[5];
    const float* gat1_ad  = (const float*)d_in[6];
    const float* gat1_b   = (const float*)d_in[7];
    const float* gat2_W   = (const float*)d_in[8];
    const float* gat2_as  = (const float*)d_in[9];
    const float* gat2_ad  = (const float*)d_in[10];
    const float* gat2_b   = (const float*)d_in[11];
    const float* mean_W   = (const float*)d_in[12];
    const float* mean_as  = (const float*)d_in[13];
    const float* mean_ad  = (const float*)d_in[14];
    const float* mean_b   = (const float*)d_in[15];
    const float* std_W    = (const float*)d_in[16];
    const float* std_as   = (const float*)d_in[17];
    const float* std_ad   = (const float*)d_in[18];
    const float* std_b    = (const float*)d_in[19];

    float* out = (float*)d_out;
    float* o_zmean = out;
    float* o_zstd  = out + 1280000;
    float* o_a1    = out + 2560000;
    float* o_a2    = out + 3920000;
    float* o_am    = out + 5280000;
    float* o_as    = out + 6640000;

    float* p_xw;
    bf16 *p_xhi, *p_xlo, *p_hhi, *p_hlo, *p_wthi, *p_wtlo;
    cudaGetSymbolAddress((void**)&p_xw, g_xw);
    cudaGetSymbolAddress((void**)&p_xhi, g_xhi);
    cudaGetSymbolAddress((void**)&p_xlo, g_xlo);
    cudaGetSymbolAddress((void**)&p_hhi, g_hhi);
    cudaGetSymbolAddress((void**)&p_hlo, g_hlo);
    cudaGetSymbolAddress((void**)&p_wthi, g_wthi);
    cudaGetSymbolAddress((void**)&p_wtlo, g_wtlo);

    cudaFuncSetAttribute(k_wmma, cudaFuncAttributeMaxDynamicSharedMemorySize, 70000);

    const int EB = 256;
    const int EG = (NEP + EB - 1) / EB;
    const int MT = (NN + 127) / 128;   // 157

    k_zero_deg<<<80, 256>>>();
    k_hist<<<EG, EB>>>(ei);
    k_scan<<<1, 1024>>>();
    k_scatter<<<EG, EB>>>(ei);
    k_xsplit<<<(NN * 128 + 255) / 256, 256>>>(x);
    k_wsplit<<<(122880 + 255) / 256, 256>>>(gcn_W, gat1_W, gat2_W, mean_W, std_W);

    // Layer 0: GCN + relu   (K=128, Ntot=64 -> smem 256*128 = 32768 B)
    k_wmma<<<dim3(MT, 1), 256, 256 * 128>>>(p_xhi, p_xlo, p_wthi + OFF_GCN, p_wtlo + OFF_GCN,
                                            p_xw, NN, 128, 64);
    k_gcn_agg<<<NN, 64>>>(p_xw, gcn_b);

    // Layer 1: GAT concat + relu  (K=64, Ntot=256 -> smem 256*64 = 16384 B)
    k_wmma<<<dim3(MT, 4), 256, 256 * 64>>>(p_hhi, p_hlo, p_wthi + OFF_GAT1, p_wtlo + OFF_GAT1,
                                           p_xw, NN, 64, 256);
    k_coef4<<<NN / 4, 256>>>(p_xw, gat1_as, gat1_ad);
    k_softmax<4><<<NN / 4, 128>>>(o_a1, nullptr);
    k_agg_concat<<<NN, 256>>>(p_xw, gat1_b);

    // Layer 2: GAT mean + relu  (K=256, Ntot=256 -> smem 256*256 = 65536 B)
    k_wmma<<<dim3(MT, 4), 256, 256 * 256>>>(p_hhi, p_hlo, p_wthi + OFF_GAT2, p_wtlo + OFF_GAT2,
                                            p_xw, NN, 256, 256);
    k_coef4<<<NN / 4, 256>>>(p_xw, gat2_as, gat2_ad);
    k_softmax<4><<<NN / 4, 128>>>(o_a2, nullptr);
    k_agg_mean<<<NN, 256>>>(p_xw, gat2_b);

    // Layers 3+4 fused: mean & std heads  (K=64, Ntot=512 -> smem 16384 B)
    k_wmma<<<dim3(MT, 8), 256, 256 * 64>>>(p_hhi, p_hlo, p_wthi + OFF_MEAN, p_wtlo + OFF_MEAN,
                                           p_xw, NN, 64, 512);
    k_coef8<<<NN / 2, 256>>>(p_xw, mean_as, mean_ad, std_as, std_ad);
    k_softmax<8><<<NN / 4, 128>>>(o_am, o_as);
    k_agg_dual<<<NN, 512>>>(p_xw, mean_b, std_b, o_zmean, o_zstd);
}

// round 10
// speedup vs baseline: 1.1376x; 1.1376x over previous
#include <cuda_runtime.h>
#include <cuda_bf16.h>
#include <mma.h>
#include <cstdint>
#include <math.h>

#define NN 20000
#define NE 320000
#define NEP 340000
#define NEG_SLOPE 0.2f

using bf16 = __nv_bfloat16;
using namespace nvcuda;

// ---------------- scratch ----------------
__device__ int   g_deg[NN];
__device__ int   g_rowptr[NN + 1];
__device__ int   g_wptr[NN];
__device__ float g_dis[NN];
__device__ int   g_src[NEP];
__device__ int   g_eid[NEP];
__device__ float g_xw[NN * 512];
__device__ bf16  g_xhi[NN * 128];
__device__ bf16  g_xlo[NN * 128];
__device__ bf16  g_hhi[NN * 256];
__device__ bf16  g_hlo[NN * 256];
__device__ bf16  g_wthi[122880];
__device__ bf16  g_wtlo[122880];
__device__ float g_als[NN * 8];
__device__ float g_ald[NN * 8];
__device__ float g_alpha[(long)NEP * 8];

// weight-transpose offsets (elements) in g_wt*  (T[n*K+k] = W[k*N+n])
#define OFF_GCN   0
#define OFF_GAT1  8192
#define OFF_GAT2  24576
#define OFF_MEAN  90112
#define OFF_STD   106496

__device__ __forceinline__ void split_store(bf16* hi, bf16* lo, long idx, float v) {
    bf16 h = __float2bfloat16(v);
    hi[idx] = h;
    lo[idx] = __float2bfloat16(v - __bfloat162float(h));
}

// ---------------- graph build ----------------
__global__ void k_zero_deg() {
    for (int i = blockIdx.x * blockDim.x + threadIdx.x; i < NN; i += gridDim.x * blockDim.x)
        g_deg[i] = 0;
}
__global__ void k_hist(const int* __restrict__ ei) {
    for (int e = blockIdx.x * blockDim.x + threadIdx.x; e < NEP; e += gridDim.x * blockDim.x) {
        int d = (e < NE) ? ei[NE + e] : (e - NE);
        atomicAdd(&g_deg[d], 1);
    }
}
__global__ void k_scan() {
    __shared__ int tmp[1024];
    const int tid = threadIdx.x;
    const int CH = (NN + 1023) / 1024;
    const int base = tid * CH;
    int sum = 0;
    for (int i = 0; i < CH; i++) { int n = base + i; if (n < NN) sum += g_deg[n]; }
    tmp[tid] = sum;
    __syncthreads();
    for (int off = 1; off < 1024; off <<= 1) {
        int v = (tid >= off) ? tmp[tid - off] : 0;
        __syncthreads();
        tmp[tid] += v;
        __syncthreads();
    }
    int run = tmp[tid] - sum;
    for (int i = 0; i < CH; i++) {
        int n = base + i;
        if (n < NN) {
            int c = g_deg[n];
            g_rowptr[n] = run;
            g_wptr[n] = run;
            g_dis[n] = (c > 0) ? rsqrtf((float)c) : 0.0f;
            run += c;
        }
    }
    if (tid == 1023) g_rowptr[NN] = run;
}
__global__ void k_scatter(const int* __restrict__ ei) {
    for (int e = blockIdx.x * blockDim.x + threadIdx.x; e < NEP; e += gridDim.x * blockDim.x) {
        int s, d;
        if (e < NE) { s = ei[e]; d = ei[NE + e]; }
        else        { s = e - NE; d = e - NE; }
        int pos = atomicAdd(&g_wptr[d], 1);
        g_src[pos] = s;
        g_eid[pos] = e;
    }
}

// ---------------- input / weight split kernels ----------------
__global__ void k_xsplit(const float* __restrict__ x) {
    long i = (long)blockIdx.x * blockDim.x + threadIdx.x;
    if (i < (long)NN * 128) split_store(g_xhi, g_xlo, i, x[i]);
}
__global__ void k_wsplit(const float* __restrict__ Wgcn, const float* __restrict__ Wg1,
                         const float* __restrict__ Wg2, const float* __restrict__ Wm,
                         const float* __restrict__ Ws) {
    int i = blockIdx.x * blockDim.x + threadIdx.x;
    if (i >= 122880) return;
    const float* W;
    int K, N, off;
    if      (i < OFF_GAT1) { W = Wgcn; K = 128; N = 64;  off = OFF_GCN;  }
    else if (i < OFF_GAT2) { W = Wg1;  K = 64;  N = 256; off = OFF_GAT1; }
    else if (i < OFF_MEAN) { W = Wg2;  K = 256; N = 256; off = OFF_GAT2; }
    else if (i < OFF_STD)  { W = Wm;   K = 64;  N = 256; off = OFF_MEAN; }
    else                   { W = Ws;   K = 64;  N = 256; off = OFF_STD;  }
    int j = i - off;
    int n = j / K, k = j % K;
    split_store(g_wthi, g_wtlo, i, W[k * N + n]);
}

// ---------------- split-bf16 wmma GEMM, smem-staged A and B ----------------
// C[M,Ntot] tile [n0,n0+64) = A[M,K] @ T[Ntot,K]^T, fp32 accum.
// D = Ahi*Bhi + Ahi*Blo + Alo*Bhi; per KC=64 chunk both A(128x64) and B(64x64)
// hi+lo staged in smem; all fragment loads via LDSM from smem.
#define KCH 64
#define GEMM_SMEM 49152
__global__ __launch_bounds__(256) void k_wmma(
    const bf16* __restrict__ Ahi, const bf16* __restrict__ Alo,
    const bf16* __restrict__ Bhi, const bf16* __restrict__ Blo,
    float* __restrict__ C, int M, int K, int Ntot)
{
    extern __shared__ bf16 sm_[];
    bf16* sAhi = sm_;             // 128*64
    bf16* sAlo = sm_ + 8192;      // 128*64
    bf16* sBhi = sm_ + 16384;     // 64*64
    bf16* sBlo = sm_ + 20480;     // 64*64
    const int m0b = blockIdx.x * 128;
    const int n0 = blockIdx.y * 64;
    const int warp = threadIdx.x >> 5;
    const int mw = m0b + warp * 16;

    wmma::fragment<wmma::accumulator, 16, 16, 16, float> acc[4];
    for (int j = 0; j < 4; j++) wmma::fill_fragment(acc[j], 0.0f);

    for (int kc = 0; kc < K; kc += KCH) {
        // cooperative loads (all threads participate; zero-pad A rows >= M)
        for (int u = threadIdx.x; u < 1024; u += 256) {
            int row = u >> 3, seg = (u & 7) * 8;
            int gm = m0b + row;
            uint4 vh = make_uint4(0, 0, 0, 0), vl = make_uint4(0, 0, 0, 0);
            if (gm < M) {
                vh = *(const uint4*)(Ahi + (long)gm * K + kc + seg);
                vl = *(const uint4*)(Alo + (long)gm * K + kc + seg);
            }
            *(uint4*)(sAhi + row * 64 + seg) = vh;
            *(uint4*)(sAlo + row * 64 + seg) = vl;
        }
        for (int u = threadIdx.x; u < 512; u += 256) {
            int row = u >> 3, seg = (u & 7) * 8;
            *(uint4*)(sBhi + row * 64 + seg) =
                *(const uint4*)(Bhi + (long)(n0 + row) * K + kc + seg);
            *(uint4*)(sBlo + row * 64 + seg) =
                *(const uint4*)(Blo + (long)(n0 + row) * K + kc + seg);
        }
        __syncthreads();
        if (mw < M) {
            for (int k = 0; k < KCH; k += 16) {
                wmma::fragment<wmma::matrix_a, 16, 16, 16, bf16, wmma::row_major> ah, al;
                wmma::load_matrix_sync(ah, sAhi + (warp * 16) * 64 + k, 64);
                wmma::load_matrix_sync(al, sAlo + (warp * 16) * 64 + k, 64);
                for (int j = 0; j < 4; j++) {
                    wmma::fragment<wmma::matrix_b, 16, 16, 16, bf16, wmma::col_major> bh, bl;
                    wmma::load_matrix_sync(bh, sBhi + (j * 16) * 64 + k, 64);
                    wmma::load_matrix_sync(bl, sBlo + (j * 16) * 64 + k, 64);
                    wmma::mma_sync(acc[j], ah, bh, acc[j]);
                    wmma::mma_sync(acc[j], ah, bl, acc[j]);
                    wmma::mma_sync(acc[j], al, bh, acc[j]);
                }
            }
        }
        __syncthreads();
    }
    if (mw < M)
        for (int j = 0; j < 4; j++)
            wmma::store_matrix_sync(C + (long)mw * Ntot + n0 + j * 16, acc[j], Ntot,
                                    wmma::mem_row_major);
}

// ---------------- GCN aggregate ----------------
__global__ void k_gcn_agg(const float* __restrict__ xw, const float* __restrict__ b) {
    int n = blockIdx.x, t = threadIdx.x;
    int beg = g_rowptr[n], end = g_rowptr[n + 1];
    float dn = g_dis[n];
    float acc = 0.0f;
    for (int j = beg; j < end; j++) {
        int s = g_src[j];
        acc = fmaf(dn * g_dis[s], xw[s * 64 + t], acc);
    }
    float v = fmaxf(acc + b[t], 0.0f);
    split_store(g_hhi, g_hlo, (long)n * 64 + t, v);
}

// ---------------- attention coefficients ----------------
__global__ void k_coef4(const float* __restrict__ xw, const float* __restrict__ asrc,
                        const float* __restrict__ adst) {
    int t = threadIdx.x;
    int n = blockIdx.x * 4 + (t >> 6);
    int u = t & 63;
    int h = u >> 4, q = u & 15;
    const float4 v  = *(const float4*)(xw + (long)n * 256 + h * 64 + q * 4);
    const float4 ws = *(const float4*)(asrc + h * 64 + q * 4);
    const float4 wd = *(const float4*)(adst + h * 64 + q * 4);
    float ps = v.x * ws.x + v.y * ws.y + v.z * ws.z + v.w * ws.w;
    float pd = v.x * wd.x + v.y * wd.y + v.z * wd.z + v.w * wd.w;
    for (int off = 8; off > 0; off >>= 1) {
        ps += __shfl_down_sync(0xffffffffu, ps, off, 16);
        pd += __shfl_down_sync(0xffffffffu, pd, off, 16);
    }
    if (q == 0) {
        g_als[n * 4 + h] = ps;
        g_ald[n * 4 + h] = pd;
    }
}
__global__ void k_coef8(const float* __restrict__ xw,
                        const float* __restrict__ as_m, const float* __restrict__ ad_m,
                        const float* __restrict__ as_s, const float* __restrict__ ad_s) {
    int t = threadIdx.x;
    int n = blockIdx.x * 2 + (t >> 7);
    int u = t & 127;
    int h = u >> 4, q = u & 15;
    const float* aws = (h < 4) ? (as_m + h * 64) : (as_s + (h - 4) * 64);
    const float* awd = (h < 4) ? (ad_m + h * 64) : (ad_s + (h - 4) * 64);
    const float4 v  = *(const float4*)(xw + (long)n * 512 + h * 64 + q * 4);
    const float4 ws = *(const float4*)(aws + q * 4);
    const float4 wd = *(const float4*)(awd + q * 4);
    float ps = v.x * ws.x + v.y * ws.y + v.z * ws.z + v.w * ws.w;
    float pd = v.x * wd.x + v.y * wd.y + v.z * wd.z + v.w * wd.w;
    for (int off = 8; off > 0; off >>= 1) {
        ps += __shfl_down_sync(0xffffffffu, ps, off, 16);
        pd += __shfl_down_sync(0xffffffffu, pd, off, 16);
    }
    if (q == 0) {
        g_als[n * 8 + h] = ps;
        g_ald[n * 8 + h] = pd;
    }
}

__device__ __forceinline__ float leaky(float x) { return x > 0.0f ? x : NEG_SLOPE * x; }

// ---------------- segment softmax ----------------
template <int H>
__global__ void k_softmax(float* __restrict__ out0, float* __restrict__ out1) {
    int warp = threadIdx.x >> 5, lane = threadIdx.x & 31;
    int n = blockIdx.x * 4 + warp;
    if (n >= NN) return;
    int beg = g_rowptr[n], end = g_rowptr[n + 1];
    float ad[H];
    for (int h = 0; h < H; h++) ad[h] = g_ald[n * H + h];
    float m[H];
    for (int h = 0; h < H; h++) m[h] = -1e30f;
    for (int j = beg + lane; j < end; j += 32) {
        int s = g_src[j];
        for (int h = 0; h < H; h++)
            m[h] = fmaxf(m[h], leaky(g_als[s * H + h] + ad[h]));
    }
    for (int h = 0; h < H; h++)
        for (int off = 16; off > 0; off >>= 1)
            m[h] = fmaxf(m[h], __shfl_xor_sync(0xffffffffu, m[h], off));
    float sum[H];
    for (int h = 0; h < H; h++) sum[h] = 0.0f;
    for (int j = beg + lane; j < end; j += 32) {
        int s = g_src[j];
        float ex[H];
        for (int h = 0; h < H; h++) {
            ex[h] = __expf(leaky(g_als[s * H + h] + ad[h]) - m[h]);
            sum[h] += ex[h];
        }
        for (int v = 0; v < H / 4; v++) {
            float4 e4 = make_float4(ex[v * 4], ex[v * 4 + 1], ex[v * 4 + 2], ex[v * 4 + 3]);
            *(float4*)&g_alpha[(long)j * H + v * 4] = e4;
        }
    }
    for (int h = 0; h < H; h++)
        for (int off = 16; off > 0; off >>= 1)
            sum[h] += __shfl_xor_sync(0xffffffffu, sum[h], off);
    float inv[H];
    for (int h = 0; h < H; h++) inv[h] = 1.0f / (sum[h] + 1e-16f);
    for (int j = beg + lane; j < end; j += 32) {
        float ex[H];
        for (int v = 0; v < H / 4; v++) {
            float4 e4 = *(const float4*)&g_alpha[(long)j * H + v * 4];
            ex[v * 4] = e4.x; ex[v * 4 + 1] = e4.y; ex[v * 4 + 2] = e4.z; ex[v * 4 + 3] = e4.w;
        }
        for (int h = 0; h < H; h++) ex[h] *= inv[h];
        for (int v = 0; v < H / 4; v++) {
            float4 e4 = make_float4(ex[v * 4], ex[v * 4 + 1], ex[v * 4 + 2], ex[v * 4 + 3]);
            *(float4*)&g_alpha[(long)j * H + v * 4] = e4;
        }
        int eid = g_eid[j];
        *(float4*)&out0[(long)eid * 4] = make_float4(ex[0], ex[1], ex[2], ex[3]);
        if (H == 8)
            *(float4*)&out1[(long)eid * 4] = make_float4(ex[4], ex[5], ex[6], ex[7]);
    }
}

// ---------------- GAT aggregates ----------------
__global__ void k_agg_concat(const float* __restrict__ xw, const float* __restrict__ b) {
    int n = blockIdx.x, t = threadIdx.x;
    int h = t >> 6;
    int beg = g_rowptr[n], end = g_rowptr[n + 1];
    float acc = 0.0f;
    for (int j = beg; j < end; j++) {
        int s = g_src[j];
        float a = g_alpha[(long)j * 4 + h];
        acc = fmaf(a, xw[(long)s * 256 + t], acc);
    }
    float v = fmaxf(acc + b[t], 0.0f);
    split_store(g_hhi, g_hlo, (long)n * 256 + t, v);
}

__global__ void k_agg_mean(const float* __restrict__ xw, const float* __restrict__ b) {
    __shared__ float sm[256];
    int n = blockIdx.x, t = threadIdx.x;
    int h = t >> 6;
    int beg = g_rowptr[n], end = g_rowptr[n + 1];
    float acc = 0.0f;
    for (int j = beg; j < end; j++) {
        int s = g_src[j];
        float a = g_alpha[(long)j * 4 + h];
        acc = fmaf(a, xw[(long)s * 256 + t], acc);
    }
    sm[t] = acc;
    __syncthreads();
    if (t < 64) {
        float v = (sm[t] + sm[t + 64] + sm[t + 128] + sm[t + 192]) * 0.25f + b[t];
        v = fmaxf(v, 0.0f);
        split_store(g_hhi, g_hlo, (long)n * 64 + t, v);
    }
}

__global__ void k_agg_dual(const float* __restrict__ xw,
                           const float* __restrict__ b_m, const float* __restrict__ b_s,
                           float* __restrict__ out_m, float* __restrict__ out_s) {
    __shared__ float sm[512];
    int n = blockIdx.x, t = threadIdx.x;
    int h = t >> 6;
    int beg = g_rowptr[n], end = g_rowptr[n + 1];
    float acc = 0.0f;
    for (int j = beg; j < end; j++) {
        int s = g_src[j];
        float a = g_alpha[(long)j * 8 + h];
        acc = fmaf(a, xw[(long)s * 512 + t], acc);
    }
    sm[t] = acc;
    __syncthreads();
    if (t < 64) {
        out_m[(long)n * 64 + t] =
            (sm[t] + sm[t + 64] + sm[t + 128] + sm[t + 192]) * 0.25f + b_m[t];
    } else if (t < 128) {
        int u = t - 64;
        out_s[(long)n * 64 + u] =
            (sm[256 + u] + sm[320 + u] + sm[384 + u] + sm[448 + u]) * 0.25f + b_s[u];
    }
}

// ---------------- host driver ----------------
extern "C" void kernel_launch(void* const* d_in, const int* in_sizes, int n_in,
                              void* d_out, int out_size) {
    const float* x        = (const float*)d_in[0];
    const int*   ei       = (const int*)d_in[1];
    const float* gcn_W    = (const float*)d_in[2];
    const float* gcn_b    = (const float*)d_in[3];
    const float* gat1_W   = (const float*)d_in[4];
    const float* gat1_as  = (const float*)d_in[5];
    const float* gat1_ad  = (const float*)d_in[6];
    const float* gat1_b   = (const float*)d_in[7];
    const float* gat2_W   = (const float*)d_in[8];
    const float* gat2_as  = (const float*)d_in[9];
    const float* gat2_ad  = (const float*)d_in[10];
    const float* gat2_b   = (const float*)d_in[11];
    const float* mean_W   = (const float*)d_in[12];
    const float* mean_as  = (const float*)d_in[13];
    const float* mean_ad  = (const float*)d_in[14];
    const float* mean_b   = (const float*)d_in[15];
    const float* std_W    = (const float*)d_in[16];
    const float* std_as   = (const float*)d_in[17];
    const float* std_ad   = (const float*)d_in[18];
    const float* std_b    = (const float*)d_in[19];

    float* out = (float*)d_out;
    float* o_zmean = out;
    float* o_zstd  = out + 1280000;
    float* o_a1    = out + 2560000;
    float* o_a2    = out + 3920000;
    float* o_am    = out + 5280000;
    float* o_as    = out + 6640000;

    float* p_xw;
    bf16 *p_xhi, *p_xlo, *p_hhi, *p_hlo, *p_wthi, *p_wtlo;
    cudaGetSymbolAddress((void**)&p_xw, g_xw);
    cudaGetSymbolAddress((void**)&p_xhi, g_xhi);
    cudaGetSymbolAddress((void**)&p_xlo, g_xlo);
    cudaGetSymbolAddress((void**)&p_hhi, g_hhi);
    cudaGetSymbolAddress((void**)&p_hlo, g_hlo);
    cudaGetSymbolAddress((void**)&p_wthi, g_wthi);
    cudaGetSymbolAddress((void**)&p_wtlo, g_wtlo);

    cudaFuncSetAttribute(k_wmma, cudaFuncAttributeMaxDynamicSharedMemorySize, GEMM_SMEM);

    const int EB = 256;
    const int EG = (NEP + EB - 1) / EB;
    const int MT = (NN + 127) / 128;   // 157

    k_zero_deg<<<80, 256>>>();
    k_hist<<<EG, EB>>>(ei);
    k_scan<<<1, 1024>>>();
    k_scatter<<<EG, EB>>>(ei);
    k_xsplit<<<(NN * 128 + 255) / 256, 256>>>(x);
    k_wsplit<<<(122880 + 255) / 256, 256>>>(gcn_W, gat1_W, gat2_W, mean_W, std_W);

    // Layer 0: GCN + relu
    k_wmma<<<dim3(MT, 1), 256, GEMM_SMEM>>>(p_xhi, p_xlo, p_wthi + OFF_GCN, p_wtlo + OFF_GCN,
                                            p_xw, NN, 128, 64);
    k_gcn_agg<<<NN, 64>>>(p_xw, gcn_b);

    // Layer 1: GAT concat + relu
    k_wmma<<<dim3(MT, 4), 256, GEMM_SMEM>>>(p_hhi, p_hlo, p_wthi + OFF_GAT1, p_wtlo + OFF_GAT1,
                                            p_xw, NN, 64, 256);
    k_coef4<<<NN / 4, 256>>>(p_xw, gat1_as, gat1_ad);
    k_softmax<4><<<NN / 4, 128>>>(o_a1, nullptr);
    k_agg_concat<<<NN, 256>>>(p_xw, gat1_b);

    // Layer 2: GAT mean + relu
    k_wmma<<<dim3(MT, 4), 256, GEMM_SMEM>>>(p_hhi, p_hlo, p_wthi + OFF_GAT2, p_wtlo + OFF_GAT2,
                                            p_xw, NN, 256, 256);
    k_coef4<<<NN / 4, 256>>>(p_xw, gat2_as, gat2_ad);
    k_softmax<4><<<NN / 4, 128>>>(o_a2, nullptr);
    k_agg_mean<<<NN, 256>>>(p_xw, gat2_b);

    // Layers 3+4 fused: mean & std heads
    k_wmma<<<dim3(MT, 8), 256, GEMM_SMEM>>>(p_hhi, p_hlo, p_wthi + OFF_MEAN, p_wtlo + OFF_MEAN,
                                            p_xw, NN, 64, 512);
    k_coef8<<<NN / 2, 256>>>(p_xw, mean_as, mean_ad, std_as, std_ad);
    k_softmax<8><<<NN / 4, 128>>>(o_am, o_as);
    k_agg_dual<<<NN, 512>>>(p_xw, mean_b, std_b, o_zmean, o_zstd);
}